// round 7
// baseline (speedup 1.0000x reference)
#include <cuda_runtime.h>
#include <cuda_bf16.h>

// LightConv1d: out[b,c,t] = sum_{k=0..6} softmax(w[h])[k] * x[b,c,t-6+k] + bias[h]
// h = c % 16. Shapes: x [8,1024,4096] f32, weight [16,1,7] f32, bias [16] f32.
//
// One CTA per row, 512 threads, 2 block-strided float4 segments per thread
// (perfect coalescing). Causal halo via warp shuffles of neighbor lanes'
// registers; only lanes 0-1 patch from global (L1/L2-resident lines).
// __launch_bounds__(512,4) pins regs<=32 -> 2048 threads/SM (full occupancy).
// Output stores use evict-first (__stcs): out is never re-read.

#define T_LEN 4096
#define KSZ   7
#define NROWS (8 * 1024)
#define NTHREADS 512
#define NSEG 2   // 512 threads * 2 segs * 4 floats = 4096 = one full row
#define FULLMASK 0xffffffffu

__global__ __launch_bounds__(NTHREADS, 4)
void lightconv1d_kernel(const float* __restrict__ x,
                        const float* __restrict__ weight,
                        const float* __restrict__ bias,
                        float* __restrict__ out)
{
    const int row  = blockIdx.x;         // b*1024 + c
    const int tid  = threadIdx.x;
    const int lane = tid & 31;

    const float* __restrict__ xr = x + (size_t)row * T_LEN;
    float* __restrict__ orow     = out + (size_t)row * T_LEN;

    // Front-batch the coalesced main loads (independent LDG.128s in flight).
    float4 v[NSEG];
    #pragma unroll
    for (int seg = 0; seg < NSEG; ++seg)
        v[seg] = reinterpret_cast<const float4*>(xr)[tid + NTHREADS * seg];

    // Softmax of the 7 shared weights for this head (L1-resident).
    const int h = row & 15;              // c % 16
    float wk[KSZ];
    float mx = -1e30f;
    #pragma unroll
    for (int k = 0; k < KSZ; ++k) {
        wk[k] = __ldg(&weight[h * KSZ + k]);
        mx = fmaxf(mx, wk[k]);
    }
    float sum = 0.0f;
    #pragma unroll
    for (int k = 0; k < KSZ; ++k) {
        wk[k] = expf(wk[k] - mx);
        sum += wk[k];
    }
    const float inv = 1.0f / sum;
    #pragma unroll
    for (int k = 0; k < KSZ; ++k) wk[k] *= inv;
    const float bv = __ldg(&bias[h]);

    #pragma unroll
    for (int seg = 0; seg < NSEG; ++seg) {
        const int t0 = seg * (NTHREADS * 4) + tid * 4;

        // win[i] = x[t0 - 6 + i], i = 0..9.
        float win[10];
        // Halo from neighbor lanes' registers:
        //   lane l-1 holds x[t0-4..t0-1], lane l-2 holds x[t0-8..t0-5].
        win[2] = __shfl_up_sync(FULLMASK, v[seg].x, 1);
        win[3] = __shfl_up_sync(FULLMASK, v[seg].y, 1);
        win[4] = __shfl_up_sync(FULLMASK, v[seg].z, 1);
        win[5] = __shfl_up_sync(FULLMASK, v[seg].w, 1);
        win[0] = __shfl_up_sync(FULLMASK, v[seg].z, 2);
        win[1] = __shfl_up_sync(FULLMASK, v[seg].w, 2);

        // Cross-warp boundary lanes patch their halo from global memory
        // (lines just loaded by the previous warp -> L1/L2 hits).
        if (lane == 0) {
            if (t0 >= 8) {
                const float2 a = *reinterpret_cast<const float2*>(xr + t0 - 6);
                const float4 b = *reinterpret_cast<const float4*>(xr + t0 - 4);
                win[0] = a.x; win[1] = a.y;
                win[2] = b.x; win[3] = b.y; win[4] = b.z; win[5] = b.w;
            } else {
                // tid==0, seg==0: causal zero padding.
                win[0] = win[1] = win[2] = win[3] = win[4] = win[5] = 0.0f;
            }
        } else if (lane == 1) {
            // delta-2 shuffle invalid for lane 1 only; win[2..5] are fine.
            if (t0 >= 8) {
                const float2 a = *reinterpret_cast<const float2*>(xr + t0 - 6);
                win[0] = a.x; win[1] = a.y;
            } else {
                // tid==1, seg==0: x[-2], x[-1] -> zeros.
                win[0] = win[1] = 0.0f;
            }
        }

        win[6] = v[seg].x; win[7] = v[seg].y; win[8] = v[seg].z; win[9] = v[seg].w;

        float a0 = bv, a1 = bv, a2 = bv, a3 = bv;
        #pragma unroll
        for (int k = 0; k < KSZ; ++k) {
            a0 = fmaf(wk[k], win[k + 0], a0);
            a1 = fmaf(wk[k], win[k + 1], a1);
            a2 = fmaf(wk[k], win[k + 2], a2);
            a3 = fmaf(wk[k], win[k + 3], a3);
        }
        float4 r; r.x = a0; r.y = a1; r.z = a2; r.w = a3;
        // Evict-first store: out is never re-read, keep L2 for x.
        __stcs(&reinterpret_cast<float4*>(orow)[tid + NTHREADS * seg], r);
    }
}

extern "C" void kernel_launch(void* const* d_in, const int* in_sizes, int n_in,
                              void* d_out, int out_size)
{
    const float* x      = (const float*)d_in[0];
    const float* weight = (const float*)d_in[1];
    const float* bias   = (const float*)d_in[2];
    float* out          = (float*)d_out;

    lightconv1d_kernel<<<NROWS, NTHREADS>>>(x, weight, bias, out);
}

// round 8
// speedup vs baseline: 1.0051x; 1.0051x over previous
#include <cuda_runtime.h>
#include <cuda_bf16.h>

// LightConv1d: out[b,c,t] = sum_{k=0..6} softmax(w[h])[k] * x[b,c,t-6+k] + bias[h]
// h = c % 16. Shapes: x [8,1024,4096] f32, weight [16,1,7] f32, bias [16] f32.
//
// R6 champion structure: one CTA per row, 256 threads, 4 block-strided float4
// segments per thread (perfect coalescing, 4 lines per LDG.128 warp instr).
// Causal halo via warp shuffles of neighbor lanes' registers; only lanes 0-1
// patch from global (L1/L2-resident lines). No SMEM, no barriers, no forced
// register cap (ptxas chooses ~39 regs; measured fastest).
// This round's only delta: evict-first (__stcs) output stores — out is never
// re-read, so keep the write stream from displacing x lines in L2.

#define T_LEN 4096
#define KSZ   7
#define NROWS (8 * 1024)
#define NTHREADS 256
#define NSEG 4   // 256 threads * 4 segs * 4 floats = 4096 = one full row
#define FULLMASK 0xffffffffu

__global__ __launch_bounds__(NTHREADS)
void lightconv1d_kernel(const float* __restrict__ x,
                        const float* __restrict__ weight,
                        const float* __restrict__ bias,
                        float* __restrict__ out)
{
    const int row  = blockIdx.x;         // b*1024 + c
    const int tid  = threadIdx.x;
    const int lane = tid & 31;

    const float* __restrict__ xr = x + (size_t)row * T_LEN;
    float* __restrict__ orow     = out + (size_t)row * T_LEN;

    // Front-batch the 4 coalesced main loads (MLP_p1 = 4).
    float4 v[NSEG];
    #pragma unroll
    for (int seg = 0; seg < NSEG; ++seg)
        v[seg] = reinterpret_cast<const float4*>(xr)[tid + NTHREADS * seg];

    // Softmax of the 7 shared weights for this head (L1-resident).
    const int h = row & 15;              // c % 16
    float wk[KSZ];
    float mx = -1e30f;
    #pragma unroll
    for (int k = 0; k < KSZ; ++k) {
        wk[k] = __ldg(&weight[h * KSZ + k]);
        mx = fmaxf(mx, wk[k]);
    }
    float sum = 0.0f;
    #pragma unroll
    for (int k = 0; k < KSZ; ++k) {
        wk[k] = expf(wk[k] - mx);
        sum += wk[k];
    }
    const float inv = 1.0f / sum;
    #pragma unroll
    for (int k = 0; k < KSZ; ++k) wk[k] *= inv;
    const float bv = __ldg(&bias[h]);

    #pragma unroll
    for (int seg = 0; seg < NSEG; ++seg) {
        const int t0 = seg * (NTHREADS * 4) + tid * 4;

        // win[i] = x[t0 - 6 + i], i = 0..9.
        float win[10];
        // Halo from neighbor lanes' registers:
        //   lane l-1 holds x[t0-4..t0-1], lane l-2 holds x[t0-8..t0-5].
        win[2] = __shfl_up_sync(FULLMASK, v[seg].x, 1);
        win[3] = __shfl_up_sync(FULLMASK, v[seg].y, 1);
        win[4] = __shfl_up_sync(FULLMASK, v[seg].z, 1);
        win[5] = __shfl_up_sync(FULLMASK, v[seg].w, 1);
        win[0] = __shfl_up_sync(FULLMASK, v[seg].z, 2);
        win[1] = __shfl_up_sync(FULLMASK, v[seg].w, 2);

        // Cross-warp boundary lanes patch their halo from global memory
        // (lines just loaded by the previous warp -> L1/L2 hits).
        if (lane == 0) {
            if (t0 >= 8) {
                const float2 a = *reinterpret_cast<const float2*>(xr + t0 - 6);
                const float4 b = *reinterpret_cast<const float4*>(xr + t0 - 4);
                win[0] = a.x; win[1] = a.y;
                win[2] = b.x; win[3] = b.y; win[4] = b.z; win[5] = b.w;
            } else {
                // tid==0, seg==0: causal zero padding.
                win[0] = win[1] = win[2] = win[3] = win[4] = win[5] = 0.0f;
            }
        } else if (lane == 1) {
            // delta-2 shuffle invalid for lane 1 only; win[2..5] are fine.
            if (t0 >= 8) {
                const float2 a = *reinterpret_cast<const float2*>(xr + t0 - 6);
                win[0] = a.x; win[1] = a.y;
            } else {
                // tid==1, seg==0: x[-2], x[-1] -> zeros.
                win[0] = win[1] = 0.0f;
            }
        }

        win[6] = v[seg].x; win[7] = v[seg].y; win[8] = v[seg].z; win[9] = v[seg].w;

        float a0 = bv, a1 = bv, a2 = bv, a3 = bv;
        #pragma unroll
        for (int k = 0; k < KSZ; ++k) {
            a0 = fmaf(wk[k], win[k + 0], a0);
            a1 = fmaf(wk[k], win[k + 1], a1);
            a2 = fmaf(wk[k], win[k + 2], a2);
            a3 = fmaf(wk[k], win[k + 3], a3);
        }
        float4 r; r.x = a0; r.y = a1; r.z = a2; r.w = a3;
        // Evict-first store: out is never re-read, keep L2 for x.
        __stcs(&reinterpret_cast<float4*>(orow)[tid + NTHREADS * seg], r);
    }
}

extern "C" void kernel_launch(void* const* d_in, const int* in_sizes, int n_in,
                              void* d_out, int out_size)
{
    const float* x      = (const float*)d_in[0];
    const float* weight = (const float*)d_in[1];
    const float* bias   = (const float*)d_in[2];
    float* out          = (float*)d_out;

    lightconv1d_kernel<<<NROWS, NTHREADS>>>(x, weight, bias, out);
}